// round 8
// baseline (speedup 1.0000x reference)
#include <cuda_runtime.h>

// AdditiveEmission: local-window (w=3) additive attention, fused single kernel.
//   q = X@Wt, k = X@Wx
//   e[i,j] = Wa . tanh(q_i + k_j + bh) + ba,  j in {i-1,i,i+1} (clipped)
//   a = softmax_window(e) (+EPS), out_i = sum_j a[i,j] * x_j
//
// B=4, L=512, D=128.
// Grid = 37 tiles x 4 batches = 148 blocks == #SMs (one wave).
// Block = 1024 threads = 16 groups of 64; thread = CHANNEL PAIR (2j, 2j+1).
//   Phase 1: disjoint row-GEMVs via packed fma.rn.f32x2 (FFMA2):
//            weights load as LDG.64 pairs; x staged in SMEM as {v,v} dups so
//            one LDS.128 = two packed x operands. g0-7: q rows (Wt),
//            g8-15: k rows (Wx). 1-2 rows per group, computed once.
//   Phase 2: group t computes query t's 3 logits (tanh + 2-warp reduce).
//   Phase 3: windowed softmax + AV, STG.64 per thread.

#define B_     4
#define L_     512
#define D_     128
#define T_     14         // queries per tile
#define TILES_ 37         // ceil(512/14)
#define KR_    16         // staged x rows: i0-1 .. i0+14
#define NQK_   (T_ + KR_) // 30 q/k rows
#define EPS_   1e-8f

typedef unsigned long long ull;

__device__ __forceinline__ ull ffma2(ull x, ull w, ull c) {
    ull r;
    asm("fma.rn.f32x2 %0, %1, %2, %3;" : "=l"(r) : "l"(x), "l"(w), "l"(c));
    return r;
}

__device__ __forceinline__ float tanh_approx(float v) {
    float r;
    asm("tanh.approx.f32 %0, %1;" : "=f"(r) : "f"(v));
    return r;
}

// NR row-GEMVs against W for this thread's channel pair (2j, 2j+1).
// xsd rows are {v,v} duplicated floats; acc/w are packed f32x2 in 64-bit regs.
template<int NR>
__device__ __forceinline__ void gemv_rows(const float2 (*xsd)[D_], float (*qk)[D_],
                                          const float* __restrict__ W,
                                          int xs0, int dst0, int j)
{
    ull acc[NR];
    #pragma unroll
    for (int r = 0; r < NR; ++r) acc[r] = 0ull;

    const ull* wp = reinterpret_cast<const ull*>(W) + j;   // pair column (2j,2j+1)

    #pragma unroll 2
    for (int e = 0; e < D_; e += 4) {
        // 4 weight pairs, front-batched (stride D_/2 ull per e-row)
        const ull w0 = wp[0 * (D_ / 2)];
        const ull w1 = wp[1 * (D_ / 2)];
        const ull w2 = wp[2 * (D_ / 2)];
        const ull w3 = wp[3 * (D_ / 2)];
        wp += 4 * (D_ / 2);

        ulonglong2 xv0[NR], xv1[NR];
        #pragma unroll
        for (int r = 0; r < NR; ++r) {
            const ulonglong2* xp = reinterpret_cast<const ulonglong2*>(&xsd[xs0 + r][e]);
            xv0[r] = xp[0];     // {x_e,x_e},{x_e+1,x_e+1}
            xv1[r] = xp[1];     // {x_e+2,..},{x_e+3,..}
        }
        #pragma unroll
        for (int r = 0; r < NR; ++r) acc[r] = ffma2(xv0[r].x, w0, acc[r]);
        #pragma unroll
        for (int r = 0; r < NR; ++r) acc[r] = ffma2(xv0[r].y, w1, acc[r]);
        #pragma unroll
        for (int r = 0; r < NR; ++r) acc[r] = ffma2(xv1[r].x, w2, acc[r]);
        #pragma unroll
        for (int r = 0; r < NR; ++r) acc[r] = ffma2(xv1[r].y, w3, acc[r]);
    }
    #pragma unroll
    for (int r = 0; r < NR; ++r)
        *reinterpret_cast<ull*>(&qk[dst0 + r][2 * j]) = acc[r];   // STS.64
}

__global__ __launch_bounds__(1024, 1)
void additive_local_attn(const float* __restrict__ x,
                         const float* __restrict__ Wt,
                         const float* __restrict__ Wx,
                         const float* __restrict__ Wa,
                         const float* __restrict__ bh,
                         const float* __restrict__ ba,
                         float* __restrict__ out)
{
    __shared__ __align__(16) float2 xsd[KR_][D_];   // x rows, {v,v} dups (16KB)
    __shared__ __align__(16) float  qk[NQK_][D_];   // rows 0..13: q; 14..29: k (15KB)
    __shared__ float sred[T_][2][3];                // per-query, per-warp-in-group partials

    const int tid = threadIdx.x;
    const int grp = tid >> 6;          // 0..15
    const int j   = tid & 63;          // channel pair index
    const int w2  = (tid >> 5) & 1;    // warp within group
    const int b   = blockIdx.y;
    const int i0  = blockIdx.x * T_;

    const float* xb = x + (size_t)b * L_ * D_;

    // ---- stage x rows [i0-1, i0+14] as {v,v} pairs ----
    #pragma unroll
    for (int idx = tid; idx < KR_ * D_; idx += 1024) {
        const int r = idx >> 7;
        const int c = idx & (D_ - 1);
        const int g = i0 - 1 + r;
        const float v = (g >= 0 && g < L_) ? xb[g * D_ + c] : 0.0f;
        xsd[r][c] = make_float2(v, v);
    }
    __syncthreads();

    // ---- phase 1: disjoint row-GEMVs (each row computed exactly once) ----
    // q-groups 0..5: rows 2g..2g+1 (xs row = q+1); 6,7: rows 12,13
    // k-groups 8..15: rows 2(g-8)..2(g-8)+1 (xs row = k), dst 14+k
    if (grp < 8) {
        if (grp < 6) gemv_rows<2>(xsd, qk, Wt, 2 * grp + 1, 2 * grp, j);
        else         gemv_rows<1>(xsd, qk, Wt, (grp + 6) + 1, grp + 6, j);
    } else {
        const int kg = grp - 8;
        gemv_rows<2>(xsd, qk, Wx, 2 * kg, T_ + 2 * kg, j);
    }
    __syncthreads();

    // ---- phase 2: group t computes query t's 3 windowed logits ----
    if (grp < T_) {
        const float2 wa2 = *reinterpret_cast<const float2*>(&Wa[2 * j]);
        const float2 bh2 = *reinterpret_cast<const float2*>(&bh[2 * j]);
        const int t = grp;
        const float2 qv = *reinterpret_cast<const float2*>(&qk[t][2 * j]);
        const float q0 = qv.x + bh2.x;
        const float q1 = qv.y + bh2.y;

        float p[3];
        #pragma unroll
        for (int jj = 0; jj < 3; ++jj) {
            const float2 kv = *reinterpret_cast<const float2*>(&qk[T_ + t + jj][2 * j]);
            p[jj] = wa2.x * tanh_approx(q0 + kv.x) + wa2.y * tanh_approx(q1 + kv.y);
        }
        #pragma unroll
        for (int off = 16; off; off >>= 1) {
            p[0] += __shfl_xor_sync(0xffffffffu, p[0], off);
            p[1] += __shfl_xor_sync(0xffffffffu, p[1], off);
            p[2] += __shfl_xor_sync(0xffffffffu, p[2], off);
        }
        if ((tid & 31) == 0) {
            sred[t][w2][0] = p[0];
            sred[t][w2][1] = p[1];
            sred[t][w2][2] = p[2];
        }
    }
    __syncthreads();

    // ---- phase 3: windowed softmax (+EPS) and AV for query t = grp ----
    if (grp < T_) {
        const int t = grp;
        const int i = i0 + t;
        if (i < L_) {
            const float ba0 = ba[0];
            float e0 = sred[t][0][0] + sred[t][1][0] + ba0;
            float e1 = sred[t][0][1] + sred[t][1][1] + ba0;
            float e2 = sred[t][0][2] + sred[t][1][2] + ba0;

            const bool v0 = (i - 1) >= 0;
            const bool v2 = (i + 1) < L_;

            float m = e1;
            if (v0) m = fmaxf(m, e0);
            if (v2) m = fmaxf(m, e2);

            const float w0 = v0 ? __expf(e0 - m) : 0.0f;
            const float w1 = __expf(e1 - m);
            const float w2v = v2 ? __expf(e2 - m) : 0.0f;
            const float inv = 1.0f / (w0 + w1 + w2v + EPS_);

            // x rows for query i are xs rows t, t+1, t+2; pick both channels
            const float4 xa = *reinterpret_cast<const float4*>(&xsd[t][2 * j]);
            const float4 xbv = *reinterpret_cast<const float4*>(&xsd[t + 1][2 * j]);
            const float4 xc = *reinterpret_cast<const float4*>(&xsd[t + 2][2 * j]);

            float2 o;
            o.x = (w0 * xa.x + w1 * xbv.x + w2v * xc.x) * inv;
            o.y = (w0 * xa.z + w1 * xbv.z + w2v * xc.z) * inv;
            *reinterpret_cast<float2*>(&out[((size_t)b * L_ + i) * D_ + 2 * j]) = o;
        }
    }
}

extern "C" void kernel_launch(void* const* d_in, const int* in_sizes, int n_in,
                              void* d_out, int out_size)
{
    const float* x  = (const float*)d_in[0];
    const float* Wt = (const float*)d_in[1];
    const float* Wx = (const float*)d_in[2];
    const float* Wa = (const float*)d_in[3];
    const float* bh = (const float*)d_in[4];
    const float* ba = (const float*)d_in[5];
    float* out = (float*)d_out;

    dim3 grid(TILES_, B_);   // 37 x 4 = 148 blocks == #SMs
    additive_local_attn<<<grid, 1024>>>(x, Wt, Wx, Wa, bh, ba, out);
}